// round 12
// baseline (speedup 1.0000x reference)
#include <cuda_runtime.h>
#include <cuda_fp16.h>
#include <cstdint>

// B=16,H=128 -> 2048 groups; per group X[128,256], D=32.
#define NTHR 256

// ---------------- SMEM (all fragment-major, zero padding) ----------------
// XF: A-frags  [rb 0..7][kt 0..15][lane] uint4(a0,a2,a1,a3)       = 65,536
// WB0/WB1: weight B-frags [ktp 0..7][nt 0..3][lane] uint4
//          (kt=2ktp uint2, kt=2ktp+1 uint2)                       = 16,384 ea
// VT0/VT1: V^T B-frags [kt 0..7][nt 0..3][lane] uint2             =  8,192 ea
// K image (scores B-frags) overlays VT1: [ntile 0..15][lane] uint4
//          (kt0 uint2, kt1 uint2)                                 =  8,192
#define XF_OFF  0
#define WB0     65536
#define WB1     81920
#define VT0     98304
#define VT1     106496
#define K_OFF   106496
#define SMEM_BYTES 114688            // 2 CTAs/SM (limit 116,224)

#define FCHUNK 16384
// weight image: [chunk 0..9][ktp][nt][lane] uint4;  0=Wq 1=Wk 2..9=Wv cols
__device__ __align__(16) unsigned char g_wimg[10 * FCHUNK];

__device__ __forceinline__ uint32_t smem_u32(const void* p) {
    uint32_t a;
    asm("{ .reg .u64 t; cvta.to.shared.u64 t, %1; cvt.u32.u64 %0, t; }" : "=r"(a) : "l"(p));
    return a;
}
__device__ __forceinline__ void cp16(void* sdst, const void* gsrc) {
    asm volatile("cp.async.cg.shared.global [%0], [%1], 16;"
                 :: "r"(smem_u32(sdst)), "l"(gsrc));
}
#define CP_COMMIT() asm volatile("cp.async.commit_group;" ::: "memory")
#define CP_WAIT0()  asm volatile("cp.async.wait_group 0;" ::: "memory")

__device__ __forceinline__ void mma16816(float* c, uint32_t a0, uint32_t a1,
                                         uint32_t a2, uint32_t a3,
                                         uint32_t b0, uint32_t b1) {
    asm volatile(
        "mma.sync.aligned.m16n8k16.row.col.f32.f16.f16.f32 "
        "{%0,%1,%2,%3},{%4,%5,%6,%7},{%8,%9},{%0,%1,%2,%3};"
        : "+f"(c[0]), "+f"(c[1]), "+f"(c[2]), "+f"(c[3])
        : "r"(a0), "r"(a1), "r"(a2), "r"(a3), "r"(b0), "r"(b1));
}
__device__ __forceinline__ uint32_t packh(float x, float y) {
    __half2 p = __floats2half2_rn(x, y);
    return *reinterpret_cast<uint32_t*>(&p);
}

// =============== prep: weights -> fp16 paired-frag image ===============
__global__ void prep_weights(const float* __restrict__ Wq, const float* __restrict__ Wk,
                             const float* __restrict__ Wv) {
    int idx = blockIdx.x * 256 + threadIdx.x;   // 10*8*4*32 = 10240
    if (idx >= 10240) return;
    int lane = idx & 31;
    int nt   = (idx >> 5) & 3;
    int ktp  = (idx >> 7) & 7;
    int chunk = idx >> 10;
    int lq = lane >> 2, q = lane & 3;
    int n = nt * 8 + lq;
    __half v[8];
    #pragma unroll
    for (int h2 = 0; h2 < 2; h2++) {
        int kb = (2 * ktp + h2) * 16;
        int ks[4] = { kb + 2*q, kb + 2*q + 1, kb + 2*q + 8, kb + 2*q + 9 };
        #pragma unroll
        for (int i = 0; i < 4; i++) {
            float w;
            if (chunk == 0)      w = Wq[ks[i] * 32 + n];
            else if (chunk == 1) w = Wk[ks[i] * 32 + n];
            else                 w = Wv[ks[i] * 256 + (chunk - 2) * 32 + n];
            v[h2 * 4 + i] = __float2half(w);
        }
    }
    *(uint4*)(g_wimg + (((chunk * 8 + ktp) * 4 + nt) * 512) + lane * 16) =
        *reinterpret_cast<uint4*>(v);
}

// =============== main: one CTA (8 warps) per (b,h) group, 2 CTAs/SM ===============
__global__ __launch_bounds__(NTHR, 2)
void attn_mma_kernel(const float* __restrict__ X,
                     const float* __restrict__ bq, const float* __restrict__ bk,
                     const float* __restrict__ bv, float* __restrict__ out) {
    extern __shared__ unsigned char sm[];
    const int t = threadIdx.x, w = t >> 5, lane = t & 31;
    const int q = lane & 3, lq = lane >> 2;
    const int R = w * 16;
    const long long g = blockIdx.x;
    const float* Xg = X + g * 32768LL;
    float* Og = out + g * 32768LL;

    // issue Wq -> WB0, Wk -> WB1
    for (int j = t; j < 1024; j += NTHR) {
        cp16(sm + WB0 + j * 16, g_wimg + j * 16);
        cp16(sm + WB1 + j * 16, g_wimg + FCHUNK + j * 16);
    }
    CP_COMMIT();

    // X load -> frag-major A image: thread builds whole 16B lane-slots
    #pragma unroll 4
    for (int s = 0; s < 16; s++) {
        int slot = s * NTHR + t;            // 0..4095
        int lf = slot & 31, ktf = (slot >> 5) & 15, rb = slot >> 9;
        int row = rb * 16 + (lf >> 2);
        int k0 = ktf * 16 + 2 * (lf & 3);
        const float* xp = Xg + row * 256 + k0;
        float2 p0 = *(const float2*)xp;            // a0: (row,   k0..k0+1)
        float2 p1 = *(const float2*)(xp + 8);      // a2: (row,   k0+8..)
        float2 p2 = *(const float2*)(xp + 2048);   // a1: (row+8, k0..)
        float2 p3 = *(const float2*)(xp + 2056);   // a3: (row+8, k0+8..)
        uint4 v = make_uint4(packh(p0.x, p0.y), packh(p1.x, p1.y),
                             packh(p2.x, p2.y), packh(p3.x, p3.y));
        *(uint4*)(sm + XF_OFF + slot * 16) = v;
    }
    CP_WAIT0();
    __syncthreads();

    const unsigned char* XW = sm + XF_OFF + (unsigned)w * 8192;   // warp's 16 rows
    const unsigned lko = (unsigned)lane * 16;
    const unsigned lko8 = (unsigned)lane * 8;

    // ---------------- fused Q + K projection ----------------
    float Cq[4][4], Ck[4][4];
    #pragma unroll
    for (int n = 0; n < 4; n++) {
        Cq[n][0] = Cq[n][1] = Cq[n][2] = Cq[n][3] = 0.f;
        Ck[n][0] = Ck[n][1] = Ck[n][2] = Ck[n][3] = 0.f;
    }
    #pragma unroll 2
    for (int ktp = 0; ktp < 8; ktp++) {
        uint4 A0 = *(const uint4*)(XW + (2 * ktp) * 512 + lko);
        uint4 A1 = *(const uint4*)(XW + (2 * ktp + 1) * 512 + lko);
        #pragma unroll
        for (int nt = 0; nt < 4; nt++) {
            uint4 wq4 = *(const uint4*)(sm + WB0 + (ktp * 4 + nt) * 512 + lko);
            uint4 wk4 = *(const uint4*)(sm + WB1 + (ktp * 4 + nt) * 512 + lko);
            mma16816(Cq[nt], A0.x, A0.z, A0.y, A0.w, wq4.x, wq4.y);
            mma16816(Cq[nt], A1.x, A1.z, A1.y, A1.w, wq4.z, wq4.w);
            mma16816(Ck[nt], A0.x, A0.z, A0.y, A0.w, wk4.x, wk4.y);
            mma16816(Ck[nt], A1.x, A1.z, A1.y, A1.w, wk4.z, wk4.w);
        }
    }
    // +bq, repack scores A-frags
    uint32_t qh[2][4];
    #pragma unroll
    for (int nt = 0; nt < 4; nt++) {
        float2 bb = *(const float2*)(bq + nt * 8 + 2 * q);
        Cq[nt][0] += bb.x; Cq[nt][1] += bb.y; Cq[nt][2] += bb.x; Cq[nt][3] += bb.y;
    }
    #pragma unroll
    for (int kt = 0; kt < 2; kt++) {
        qh[kt][0] = packh(Cq[2*kt][0],   Cq[2*kt][1]);
        qh[kt][1] = packh(Cq[2*kt][2],   Cq[2*kt][3]);
        qh[kt][2] = packh(Cq[2*kt+1][0], Cq[2*kt+1][1]);
        qh[kt][3] = packh(Cq[2*kt+1][2], Cq[2*kt+1][3]);
    }

    // K write (+bk) into K frag image (region VT1 — untouched so far)
    #pragma unroll
    for (int nt = 0; nt < 4; nt++) {
        float2 bb = *(const float2*)(bk + nt * 8 + 2 * q);
        unsigned s0 = K_OFF + (unsigned)(2 * w) * 512 + (unsigned)(lq * 4 + q) * 16 + nt * 4;
        *(uint32_t*)(sm + s0)       = packh(Ck[nt][0] + bb.x, Ck[nt][1] + bb.y);
        *(uint32_t*)(sm + s0 + 512) = packh(Ck[nt][2] + bb.x, Ck[nt][3] + bb.y);
    }
    __syncthreads();   // proj reads of WB0/WB1 done; K writes done

    // issue Wv0 -> WB0, Wv1 -> WB1
    for (int j = t; j < 1024; j += NTHR) {
        cp16(sm + WB0 + j * 16, g_wimg + 2 * FCHUNK + j * 16);
        cp16(sm + WB1 + j * 16, g_wimg + 3 * FCHUNK + j * 16);
    }
    CP_COMMIT();
    CP_WAIT0();
    __syncthreads();   // K visible to all; Wv0/Wv1 visible

    // ---------------- scores S = Q @ K^T ----------------
    float Cs[16][4];
    #pragma unroll
    for (int n = 0; n < 16; n++) { Cs[n][0] = Cs[n][1] = Cs[n][2] = Cs[n][3] = 0.f; }
    #pragma unroll
    for (int ng = 0; ng < 4; ng++) {
        #pragma unroll
        for (int ni = 0; ni < 4; ni++) {
            int nt = ng * 4 + ni;
            uint4 kk = *(const uint4*)(sm + K_OFF + (unsigned)nt * 512 + lko);
            mma16816(Cs[nt], qh[0][0], qh[0][1], qh[0][2], qh[0][3], kk.x, kk.y);
            mma16816(Cs[nt], qh[1][0], qh[1][1], qh[1][2], qh[1][3], kk.z, kk.w);
        }
    }

    // ---------------- softmax (registers + quad shuffles) ----------------
    {
        float m0 = -1e30f, m1 = -1e30f;
        #pragma unroll
        for (int nt = 0; nt < 16; nt++) {
            m0 = fmaxf(m0, fmaxf(Cs[nt][0], Cs[nt][1]));
            m1 = fmaxf(m1, fmaxf(Cs[nt][2], Cs[nt][3]));
        }
        m0 = fmaxf(m0, __shfl_xor_sync(0xffffffffu, m0, 1));
        m0 = fmaxf(m0, __shfl_xor_sync(0xffffffffu, m0, 2));
        m1 = fmaxf(m1, __shfl_xor_sync(0xffffffffu, m1, 1));
        m1 = fmaxf(m1, __shfl_xor_sync(0xffffffffu, m1, 2));
        float s0 = 0.f, s1 = 0.f;
        #pragma unroll
        for (int nt = 0; nt < 16; nt++) {
            Cs[nt][0] = __expf(Cs[nt][0] - m0); Cs[nt][1] = __expf(Cs[nt][1] - m0);
            Cs[nt][2] = __expf(Cs[nt][2] - m1); Cs[nt][3] = __expf(Cs[nt][3] - m1);
            s0 += Cs[nt][0] + Cs[nt][1];
            s1 += Cs[nt][2] + Cs[nt][3];
        }
        s0 += __shfl_xor_sync(0xffffffffu, s0, 1);
        s0 += __shfl_xor_sync(0xffffffffu, s0, 2);
        s1 += __shfl_xor_sync(0xffffffffu, s1, 1);
        s1 += __shfl_xor_sync(0xffffffffu, s1, 2);
        const float i0 = 1.f / s0, i1 = 1.f / s1;
        #pragma unroll
        for (int nt = 0; nt < 16; nt++) {
            Cs[nt][0] *= i0; Cs[nt][1] *= i0; Cs[nt][2] *= i1; Cs[nt][3] *= i1;
        }
    }

    // repack attn A-frags
    uint32_t ah[8][4];
    #pragma unroll
    for (int kt = 0; kt < 8; kt++) {
        ah[kt][0] = packh(Cs[2*kt][0],   Cs[2*kt][1]);
        ah[kt][1] = packh(Cs[2*kt][2],   Cs[2*kt][3]);
        ah[kt][2] = packh(Cs[2*kt+1][0], Cs[2*kt+1][1]);
        ah[kt][3] = packh(Cs[2*kt+1][2], Cs[2*kt+1][3]);
    }

    // V-transpose constants (shfl pair exchange; writes land as exact B-frags)
    const int j2 = 2 * (lq >> 1);
    const bool oddlq = (lq & 1);
    // VT store slot for (col cc): lane_slot = (cc&7)*4 + (lq>>1); frag (kt=w, nt=cc>>3)
    const unsigned vslotbase = (unsigned)((2 * q + (oddlq ? 1 : 0)) * 4 + (lq >> 1)) * 8;

    // ---- Vproj(0) + VTstore(0) ----
    float Cv[4][4];
    {
        #pragma unroll
        for (int n = 0; n < 4; n++) { Cv[n][0] = Cv[n][1] = Cv[n][2] = Cv[n][3] = 0.f; }
        #pragma unroll 2
        for (int ktp = 0; ktp < 8; ktp++) {
            uint4 A0 = *(const uint4*)(XW + (2 * ktp) * 512 + lko);
            uint4 A1 = *(const uint4*)(XW + (2 * ktp + 1) * 512 + lko);
            #pragma unroll
            for (int nt = 0; nt < 4; nt++) {
                uint4 wf = *(const uint4*)(sm + WB0 + (ktp * 4 + nt) * 512 + lko);
                mma16816(Cv[nt], A0.x, A0.z, A0.y, A0.w, wf.x, wf.y);
                mma16816(Cv[nt], A1.x, A1.z, A1.y, A1.w, wf.z, wf.w);
            }
        }
        #pragma unroll
        for (int nt = 0; nt < 4; nt++) {
            float v0 = Cv[nt][0], v1 = Cv[nt][1], v2 = Cv[nt][2], v3 = Cv[nt][3];
            float sendA = oddlq ? v0 : v1;
            float recvA = __shfl_xor_sync(0xffffffffu, sendA, 4);
            float sendB = oddlq ? v2 : v3;
            float recvB = __shfl_xor_sync(0xffffffffu, sendB, 4);
            float a0 = oddlq ? recvA : v0, a1 = oddlq ? v1 : recvA;   // tokens R+j2, +1
            float b0 = oddlq ? recvB : v2, b1 = oddlq ? v3 : recvB;   // tokens R+8+j2, +1
            unsigned fb = VT0 + (unsigned)(w * 4 + nt) * 256 + vslotbase;
            *(uint32_t*)(sm + fb)     = packh(a0, a1);   // b0 word
            *(uint32_t*)(sm + fb + 4) = packh(b0, b1);   // b1 word
        }
    }

    // ---------------- pipelined chunk loop: ONE barrier per chunk ----------------
    // Invariants at sync_i: VT(i-1) stored; weights(i) landed (CP_WAIT0 by all);
    // readers of buf((i+1)&1) [Vproj(i-1)] and of vt(i&1) [AV(i-2)] are done.
    #pragma unroll 1
    for (int i = 1; i <= 8; i++) {
        CP_WAIT0();
        __syncthreads();
        if (i <= 6) {   // prefetch weights(i+1) into the buffer Vproj(i-1) just freed
            unsigned dst = ((i + 1) & 1) ? WB1 : WB0;
            const unsigned char* src = g_wimg + (unsigned)(3 + i) * FCHUNK;
            for (int j = t; j < 1024; j += NTHR) cp16(sm + dst + j * 16, src + j * 16);
            CP_COMMIT();
        }

        // ---- AV(i-1): O chunk = attn @ V ----
        {
            const unsigned vt = ((i - 1) & 1) ? VT1 : VT0;
            float Co[4][4];
            #pragma unroll
            for (int n = 0; n < 4; n++) { Co[n][0] = Co[n][1] = Co[n][2] = Co[n][3] = 0.f; }
            #pragma unroll
            for (int kt = 0; kt < 8; kt++) {
                #pragma unroll
                for (int nt = 0; nt < 4; nt++) {
                    uint2 bh = *(const uint2*)(sm + vt + (unsigned)(kt * 4 + nt) * 256 + lko8);
                    mma16816(Co[nt], ah[kt][0], ah[kt][1], ah[kt][2], ah[kt][3], bh.x, bh.y);
                }
            }
            #pragma unroll
            for (int nt = 0; nt < 4; nt++) {
                int col = (i - 1) * 32 + nt * 8 + 2 * q;
                float2 bb = *(const float2*)(bv + col);
                *(float2*)(Og + (long long)(R + lq) * 256 + col) =
                    make_float2(Co[nt][0] + bb.x, Co[nt][1] + bb.y);
                *(float2*)(Og + (long long)(R + 8 + lq) * 256 + col) =
                    make_float2(Co[nt][2] + bb.x, Co[nt][3] + bb.y);
            }
        }

        // ---- Vproj(i) + VTstore(i) ----
        if (i <= 7) {
            const unsigned buf = (i & 1) ? WB1 : WB0;
            #pragma unroll
            for (int n = 0; n < 4; n++) { Cv[n][0] = Cv[n][1] = Cv[n][2] = Cv[n][3] = 0.f; }
            #pragma unroll 2
            for (int ktp = 0; ktp < 8; ktp++) {
                uint4 A0 = *(const uint4*)(XW + (2 * ktp) * 512 + lko);
                uint4 A1 = *(const uint4*)(XW + (2 * ktp + 1) * 512 + lko);
                #pragma unroll
                for (int nt = 0; nt < 4; nt++) {
                    uint4 wf = *(const uint4*)(sm + buf + (ktp * 4 + nt) * 512 + lko);
                    mma16816(Cv[nt], A0.x, A0.z, A0.y, A0.w, wf.x, wf.y);
                    mma16816(Cv[nt], A1.x, A1.z, A1.y, A1.w, wf.z, wf.w);
                }
            }
            const unsigned vtw = (i & 1) ? VT1 : VT0;
            #pragma unroll
            for (int nt = 0; nt < 4; nt++) {
                float v0 = Cv[nt][0], v1 = Cv[nt][1], v2 = Cv[nt][2], v3 = Cv[nt][3];
                float sendA = oddlq ? v0 : v1;
                float recvA = __shfl_xor_sync(0xffffffffu, sendA, 4);
                float sendB = oddlq ? v2 : v3;
                float recvB = __shfl_xor_sync(0xffffffffu, sendB, 4);
                float a0 = oddlq ? recvA : v0, a1 = oddlq ? v1 : recvA;
                float b0 = oddlq ? recvB : v2, b1 = oddlq ? v3 : recvB;
                unsigned fb = vtw + (unsigned)(w * 4 + nt) * 256 + vslotbase;
                *(uint32_t*)(sm + fb)     = packh(a0, a1);
                *(uint32_t*)(sm + fb + 4) = packh(b0, b1);
            }
        }
    }
}

extern "C" void kernel_launch(void* const* d_in, const int* in_sizes, int n_in,
                              void* d_out, int out_size) {
    const float* X  = (const float*)d_in[0];
    const float* Wq = (const float*)d_in[1];
    const float* bq = (const float*)d_in[2];
    const float* Wk = (const float*)d_in[3];
    const float* bk = (const float*)d_in[4];
    const float* Wv = (const float*)d_in[5];
    const float* bv = (const float*)d_in[6];
    float* out = (float*)d_out;

    const int groups = in_sizes[0] / (128 * 256);   // 2048

    prep_weights<<<40, 256>>>(Wq, Wk, Wv);

    cudaFuncSetAttribute(attn_mma_kernel,
                         cudaFuncAttributeMaxDynamicSharedMemorySize, SMEM_BYTES);
    attn_mma_kernel<<<groups, NTHR, SMEM_BYTES>>>(X, bq, bk, bv, out);
}